// round 13
// baseline (speedup 1.0000x reference)
#include <cuda_runtime.h>
#include <cuda_bf16.h>
#include <cstdint>

#define DIMD 128
#define SAMP 12
#define RPT  10            // item rows per tile (divides 3200 and 38400 exactly)
#define MROWS 120          // GEMM rows per tile (padded to 128 in the A planes)
#define NT   512           // 16 warps; warp grid 4(m)x4(n): m32 x n32 per warp

// ---- smem byte offsets (dynamic) ----
#define NB0_OFF   0          // nb fp32 [120][128], buffer 0              61440
#define NB1_OFF   61440      // buffer 1                                  61440
#define AHI_OFF   122880     // A bf16 hi [128][128] swizzled             32768
#define ALO_OFF   155648     // A bf16 lo                                 32768
#define IT0_OFF   188416     // item fp32 [10][128] buf0                   5120
#define IT1_OFF   193536     // buf1                                       5120
#define NW0_OFF   198656     // 120 floats buf0                             512
#define NW1_OFF   199168     // buf1                                        512
#define LGP_OFF   199680     // logit partials [16 warps][128]             8192
#define LG_OFF    207872     // 120 logits                                  512
#define AL_OFF    208384     // 120 alphas                                  512
#define BIAS_OFF  208896     // 128 floats (W1 row D)                       512
#define W2_OFF    209408     // 128 floats                                  512
#define SMEM_TOTAL 209920
// W1^T bf16 hi/lo staging overlaps the NB region (read once before the loop)
#define BSTG_HI   0
#define BSTG_LO   32768

static __device__ __forceinline__ uint32_t smem_u32(const void* p) {
    uint32_t a;
    asm("{ .reg .u64 t; cvta.to.shared.u64 t, %1; cvt.u32.u64 %0, t; }" : "=r"(a) : "l"(p));
    return a;
}
static __device__ __forceinline__ void ldsm4(uint32_t &r0, uint32_t &r1, uint32_t &r2, uint32_t &r3,
                                             uint32_t addr) {
    asm volatile("ldmatrix.sync.aligned.m8n8.x4.shared.b16 {%0,%1,%2,%3}, [%4];"
                 : "=r"(r0), "=r"(r1), "=r"(r2), "=r"(r3) : "r"(addr));
}
static __device__ __forceinline__ void mma_bf16(float* d, const uint32_t* a, uint32_t b0, uint32_t b1) {
    asm volatile("mma.sync.aligned.m16n8k16.row.col.f32.bf16.bf16.f32 "
                 "{%0,%1,%2,%3}, {%4,%5,%6,%7}, {%8,%9}, {%0,%1,%2,%3};"
                 : "+f"(d[0]), "+f"(d[1]), "+f"(d[2]), "+f"(d[3])
                 : "r"(a[0]), "r"(a[1]), "r"(a[2]), "r"(a[3]), "r"(b0), "r"(b1));
}
static __device__ __forceinline__ void cp16(uint32_t smem_addr, const void* gmem) {
    asm volatile("cp.async.cg.shared.global [%0], [%1], 16;" :: "r"(smem_addr), "l"(gmem));
}
static __device__ __forceinline__ void cp_commit() {
    asm volatile("cp.async.commit_group;" ::: "memory");
}
static __device__ __forceinline__ void cp_wait0() {
    asm volatile("cp.async.wait_group 0;" ::: "memory");
}

// ---- scratch (no allocations allowed: device globals) ----
__device__ float g_a0[64*50*128];
__device__ float g_a1[64*600*128];
__device__ float g_b0[64*50*128];

// Prefetch one tile's (nb, item, nw) into smem buffer via cp.async. NT=512.
static __device__ __forceinline__ void prefetch_tile(
    uint32_t smb, uint32_t nbo, uint32_t ito, uint32_t nwo,
    const float* __restrict__ item, const float* __restrict__ nb,
    const float* __restrict__ nw, int rowBase, int tid)
{
    const float4* nbsrc = (const float4*)nb + (size_t)rowBase*(SAMP*32);
    #pragma unroll
    for (int k = 0; k < 7; k++)                        // 3584 granules
        cp16(smb + nbo + (uint32_t)(tid + k*NT)*16u, nbsrc + tid + k*NT);
    if (tid < 256)                                     // tail 256 -> 3840 total
        cp16(smb + nbo + (uint32_t)(tid + 7*NT)*16u, nbsrc + tid + 7*NT);
    const float4* itsrc = (const float4*)item + (size_t)rowBase*32;
    if (tid < 320) cp16(smb + ito + (uint32_t)tid*16u, itsrc + tid);
    const float4* nwsrc = (const float4*)(nw + (size_t)rowBase*SAMP);
    if (tid < 30) cp16(smb + nwo + (uint32_t)tid*16u, nwsrc + tid);
}

// Two independent attention-aggregate stages in one persistent launch.
// Tiles [0, tiles0) use set 0; tiles [tiles0, tilesTotal) use set 1.
__global__ void __launch_bounds__(NT, 1)
agg_kernel(const float* __restrict__ item0, const float* __restrict__ nb0a,
           const float* __restrict__ nw0a,  float* __restrict__ out0, int tiles0,
           const float* __restrict__ item1, const float* __restrict__ nb1a,
           const float* __restrict__ nw1a,  float* __restrict__ out1, int tilesTotal,
           const float* __restrict__ w1,    const float* __restrict__ w2)
{
    extern __shared__ __align__(128) char sm[];
    const uint32_t smb = smem_u32(sm);
    const int tid  = threadIdx.x;
    const int lane = tid & 31;
    const int warp = tid >> 5;          // 0..15
    const int wm   = warp >> 2;         // m-strip: rows [32wm, 32wm+32)
    const int wn   = warp & 3;          // n-slice: cols [32wn, 32wn+32)

    // ---- startup: stage W1^T hi/lo bf16 (swizzled) into the NB region ----
    for (int i = tid; i < DIMD*DIMD; i += NT) {
        int d = i >> 7, n = i & 127;                 // w1[d][n]
        float w = w1[i];
        __nv_bfloat16 hb = __float2bfloat16(w);
        __nv_bfloat16 lb = __float2bfloat16(w - __bfloat162float(hb));
        uint32_t off = (uint32_t)n*256u + ((uint32_t)(((d>>3) ^ (n & 7))) << 4) + ((uint32_t)(d & 7) << 1);
        *(__nv_bfloat16*)(sm + BSTG_HI + off) = hb;
        *(__nv_bfloat16*)(sm + BSTG_LO + off) = lb;
    }
    if (tid < DIMD) {
        ((float*)(sm + BIAS_OFF))[tid] = w1[DIMD*DIMD + tid];
        ((float*)(sm + W2_OFF))[tid]   = w2[tid];
    }
    __syncthreads();

    // ---- load B fragments for this warp's 4 n8-blocks into registers ----
    // One ldsm4 covers one n8 block over two k16-steps (q=2p, 2p+1).
    uint32_t bh[4][8][2], bl[4][8][2];
    {
        const uint32_t l7  = (uint32_t)(lane & 7);
        const uint32_t ck4 = ((uint32_t)lane >> 3) & 3;   // k8-chunk within group of 4
        #pragma unroll
        for (int j = 0; j < 4; j++) {
            const uint32_t row8 = (uint32_t)(wn*32 + j*8) + l7;
            const uint32_t rOff = row8 * 256u;
            const uint32_t swz  = row8 & 7;
            #pragma unroll
            for (int p = 0; p < 4; p++) {
                const uint32_t term = rOff + ((((uint32_t)(4*p) + ck4) ^ swz) << 4);
                ldsm4(bh[j][2*p][0], bh[j][2*p][1], bh[j][2*p+1][0], bh[j][2*p+1][1], smb + BSTG_HI + term);
                ldsm4(bl[j][2*p][0], bl[j][2*p][1], bl[j][2*p+1][0], bl[j][2*p+1][1], smb + BSTG_LO + term);
            }
        }
    }
    __syncthreads();   // staging region free; becomes nb buffers

    // ---- zero A-plane rows 120..127 (never written per-tile) ----
    if (tid < 256) {
        const uint32_t plane = (tid < 128) ? AHI_OFF : ALO_OFF;
        const int idx = tid & 127;
        *(float4*)(sm + plane + 120*256 + idx*16) = make_float4(0.f,0.f,0.f,0.f);
    }

    const float* nwb[2]   = { (const float*)(sm + NW0_OFF), (const float*)(sm + NW1_OFF) };
    const float* nbb[2]   = { (const float*)(sm + NB0_OFF), (const float*)(sm + NB1_OFF) };
    const char*  itb[2]   = { sm + IT0_OFF, sm + IT1_OFF };
    const uint32_t nbOffB[2] = { NB0_OFF, NB1_OFF };
    const uint32_t itOffB[2] = { IT0_OFF, IT1_OFF };
    const uint32_t nwOffB[2] = { NW0_OFF, NW1_OFF };
    const float* biasf = (const float*)(sm + BIAS_OFF);
    const float* w2f   = (const float*)(sm + W2_OFF);
    float* lgpart = (float*)(sm + LGP_OFF);
    float* lgf    = (float*)(sm + LG_OFF);
    float* alf    = (float*)(sm + AL_OFF);

    // per-lane A-fragment addressing constants
    const uint32_t aLaneRow = (uint32_t)(lane & 15) * 256u;
    const uint32_t aCk      = (uint32_t)(lane >> 4);
    const uint32_t aSwz     = (uint32_t)(lane & 7);

    // ---- preloop: prefetch first tile into buffer 0 ----
    {
        const int ti = blockIdx.x;
        const int rb = (ti < tiles0) ? ti*RPT : (ti - tiles0)*RPT;
        const float* it  = (ti < tiles0) ? item0 : item1;
        const float* nbp = (ti < tiles0) ? nb0a : nb1a;
        const float* nwp = (ti < tiles0) ? nw0a : nw1a;
        prefetch_tile(smb, NB0_OFF, IT0_OFF, NW0_OFF, it, nbp, nwp, rb, tid);
        cp_commit();
    }

    int cur = 0;
    for (int ti = blockIdx.x; ti < tilesTotal; ti += gridDim.x) {
        const int rowBase = (ti < tiles0) ? ti*RPT : (ti - tiles0)*RPT;
        float* outp = (ti < tiles0) ? out0 : out1;

        cp_wait0();
        __syncthreads();                 // buffer[cur] ready for all threads

        // ---- convert: A = bf16 hi/lo(item ⊙ nb) into swizzled planes ----
        {
            const float4* nbq = (const float4*)nbb[cur];
            const char* itc = itb[cur];
            #pragma unroll
            for (int k = 0; k < 8; k++) {            // 3840 granules (tail at k=7)
                const int i = tid + k*NT;
                if (k == 7 && i >= MROWS*32) break;
                const int rs = i >> 5, j = i & 31;
                float4 v  = nbq[i];
                float4 it = *(const float4*)(itc + (size_t)(rs/SAMP)*512 + (size_t)j*16);
                float m0 = v.x*it.x, m1 = v.y*it.y, m2 = v.z*it.z, m3 = v.w*it.w;
                __nv_bfloat162 h01 = __floats2bfloat162_rn(m0, m1);
                __nv_bfloat162 h23 = __floats2bfloat162_rn(m2, m3);
                float2 f01 = __bfloat1622float2(h01);
                float2 f23 = __bfloat1622float2(h23);
                __nv_bfloat162 l01 = __floats2bfloat162_rn(m0 - f01.x, m1 - f01.y);
                __nv_bfloat162 l23 = __floats2bfloat162_rn(m2 - f23.x, m3 - f23.y);
                uint32_t off = (uint32_t)rs*256u + ((uint32_t)(((j>>1) ^ (rs & 7))) << 4) + ((uint32_t)(j & 1) << 3);
                *(__nv_bfloat162*)(sm + AHI_OFF + off)     = h01;
                *(__nv_bfloat162*)(sm + AHI_OFF + off + 4) = h23;
                *(__nv_bfloat162*)(sm + ALO_OFF + off)     = l01;
                *(__nv_bfloat162*)(sm + ALO_OFF + off + 4) = l23;
            }
        }
        __syncthreads();                 // A planes ready; buffer[cur^1] free

        // ---- prefetch next tile into buffer[cur^1] (overlaps MMA+epilogue) ----
        {
            const int tn = ti + gridDim.x;
            if (tn < tilesTotal) {
                const int rb2 = (tn < tiles0) ? tn*RPT : (tn - tiles0)*RPT;
                const float* it  = (tn < tiles0) ? item0 : item1;
                const float* nbp = (tn < tiles0) ? nb0a : nb1a;
                const float* nwp = (tn < tiles0) ? nw0a : nw1a;
                prefetch_tile(smb, nbOffB[cur^1], itOffB[cur^1], nwOffB[cur^1], it, nbp, nwp, rb2, tid);
                cp_commit();
            }
        }

        // ---- MMA: warp computes D[32wm:32wm+32, 32wn:32wn+32] ----
        float d[2][4][4];
        #pragma unroll
        for (int s = 0; s < 2; s++)
            #pragma unroll
            for (int j = 0; j < 4; j++)
                #pragma unroll
                for (int i = 0; i < 4; i++) d[s][j][i] = 0.f;

        #pragma unroll
        for (int q = 0; q < 8; q++) {
            const uint32_t koff = ((((uint32_t)(2*q) + aCk) ^ aSwz) << 4);
            #pragma unroll
            for (int s = 0; s < 2; s++) {
                const uint32_t aoff = (uint32_t)(wm*2 + s)*4096u + aLaneRow + koff;
                uint32_t ah[4], al[4];
                ldsm4(ah[0], ah[1], ah[2], ah[3], smb + AHI_OFF + aoff);
                ldsm4(al[0], al[1], al[2], al[3], smb + ALO_OFF + aoff);
                #pragma unroll
                for (int j = 0; j < 4; j++) {
                    mma_bf16(d[s][j], ah, bh[j][q][0], bh[j][q][1]);
                    mma_bf16(d[s][j], al, bh[j][q][0], bh[j][q][1]);
                    mma_bf16(d[s][j], ah, bl[j][q][0], bl[j][q][1]);
                }
            }
        }

        // ---- logit partials: bias*nw + leaky + dot(w2) over this warp's 32 cols ----
        {
            const int lq = lane & 3;
            const int rq = lane >> 2;
            const float* nwf = nwb[cur];
            #pragma unroll
            for (int s = 0; s < 2; s++) {
                const int r0 = wm*32 + s*16 + rq;      // < 120 always (max 119)
                const int r1 = r0 + 8;
                const float nw0 = nwf[r0];
                const float nw1 = nwf[r1 < MROWS ? r1 : 0];
                float lg0 = 0.f, lg1 = 0.f;
                #pragma unroll
                for (int j = 0; j < 4; j++) {
                    const int c0 = wn*32 + j*8 + lq*2;
                    const float b0v = biasf[c0], b1v = biasf[c0+1];
                    const float v0  = w2f[c0],   v1  = w2f[c0+1];
                    float y;
                    y = d[s][j][0] + nw0*b0v; y = fmaxf(y,0.f) + 0.2f*fminf(y,0.f); lg0 = fmaf(y, v0, lg0);
                    y = d[s][j][1] + nw0*b1v; y = fmaxf(y,0.f) + 0.2f*fminf(y,0.f); lg0 = fmaf(y, v1, lg0);
                    y = d[s][j][2] + nw1*b0v; y = fmaxf(y,0.f) + 0.2f*fminf(y,0.f); lg1 = fmaf(y, v0, lg1);
                    y = d[s][j][3] + nw1*b1v; y = fmaxf(y,0.f) + 0.2f*fminf(y,0.f); lg1 = fmaf(y, v1, lg1);
                }
                lg0 += __shfl_xor_sync(0xffffffffu, lg0, 1);
                lg0 += __shfl_xor_sync(0xffffffffu, lg0, 2);
                lg1 += __shfl_xor_sync(0xffffffffu, lg1, 1);
                lg1 += __shfl_xor_sync(0xffffffffu, lg1, 2);
                if (lq == 0) {
                    lgpart[warp*128 + r0] = lg0;
                    if (r1 < MROWS) lgpart[warp*128 + r1] = lg1;
                }
            }
        }
        __syncthreads();

        // ---- reduce partials across the 4 n-warps of each m-strip, softmax ----
        if (tid < MROWS) {
            const int wmr = tid >> 5;          // m-strip of this row
            float lg = 0.f;
            #pragma unroll
            for (int k = 0; k < 4; k++) lg += lgpart[(wmr*4 + k)*128 + tid];
            lgf[tid] = lg;
        }
        __syncthreads();
        if (tid < RPT) {
            const float* lg = lgf + tid*SAMP;
            float l[SAMP], mx = -1e30f;
            #pragma unroll
            for (int s = 0; s < SAMP; s++) { l[s] = lg[s]; mx = fmaxf(mx, l[s]); }
            float sum = 0.f;
            #pragma unroll
            for (int s = 0; s < SAMP; s++) { l[s] = __expf(l[s] - mx); sum += l[s]; }
            float inv = 1.f / sum;
            #pragma unroll
            for (int s = 0; s < SAMP; s++) alf[tid*SAMP + s] = l[s] * inv;
        }
        __syncthreads();

        // ---- weighted sum of raw nb rows from the prefetch buffer ----
        {
            const int col = tid & 127;
            const int grp = tid >> 7;           // 0..3
            const float* nbf = nbb[cur];
            #pragma unroll
            for (int r = grp; r < RPT; r += 4) {
                float acc = 0.f;
                #pragma unroll
                for (int s = 0; s < SAMP; s++)
                    acc = fmaf(alf[r*SAMP + s], nbf[(size_t)(r*SAMP + s)*DIMD + col], acc);
                outp[(size_t)(rowBase + r)*DIMD + col] = acc;
            }
        }
        __syncthreads();   // epilogue readers done before next convert overwrites
        cur ^= 1;
    }
}

// Final gating, persistent with w3/w4 resident in smem:
//   out = (1-sig)*h + sig*agg, sig = sigmoid(h@w3 + agg@w4), agg = a0*s0 + b0*s1
#define FIN_SMEM ((2*128*128 + 4*128) * 4)   // w3s + w4s + hrow(2x128) + arow(2x128)
__global__ void __launch_bounds__(256, 1)
final_kernel(const float* __restrict__ hidden,
             const float* __restrict__ a0,
             const float* __restrict__ b0,
             const float* __restrict__ w3,
             const float* __restrict__ w4,
             const float* __restrict__ sw,
             float* __restrict__ out,
             int numRows)                       // even
{
    extern __shared__ float fsm[];
    float* w3s  = fsm;                 // 16384 floats
    float* w4s  = fsm + 16384;         // 16384 floats
    float* hrow = fsm + 32768;         // 2 x 128
    float* arow = fsm + 33024;         // 2 x 128  (ends at 33280 = FIN_SMEM/4)
    const int tid = threadIdx.x;
    const float s0 = sw[0], s1 = sw[1];

    for (int i = tid; i < 16384; i += 256) { w3s[i] = w3[i]; w4s[i] = w4[i]; }
    __syncthreads();

    const int col = tid & 127;
    const int g   = tid >> 7;          // row within pair

    for (int rp = blockIdx.x*2; rp < numRows; rp += gridDim.x*2) {
        const int row = rp + g;
        hrow[g*128 + col] = hidden[(size_t)row*DIMD + col];
        arow[g*128 + col] = fmaf(a0[(size_t)row*DIMD + col], s0,
                                 b0[(size_t)row*DIMD + col] * s1);
        __syncthreads();
        float z = 0.f;
        const float* hr = hrow + g*128;
        const float* ar = arow + g*128;
        #pragma unroll 8
        for (int d = 0; d < DIMD; d++)
            z = fmaf(hr[d], w3s[d*DIMD + col], fmaf(ar[d], w4s[d*DIMD + col], z));
        float sig = 1.f / (1.f + __expf(-z));
        out[(size_t)row*DIMD + col] = (1.f - sig)*hr[col] + sig*ar[col];
        __syncthreads();
    }
}

extern "C" void kernel_launch(void* const* d_in, const int* in_sizes, int n_in,
                              void* d_out, int out_size)
{
    const float* hidden = (const float*)d_in[0];
    const float* nh1    = (const float*)d_in[1];
    const float* nh2    = (const float*)d_in[2];
    const float* nw0    = (const float*)d_in[3];
    const float* nw1    = (const float*)d_in[4];
    const float* w1     = (const float*)d_in[5];
    const float* w2     = (const float*)d_in[6];
    const float* w3     = (const float*)d_in[7];
    const float* w4     = (const float*)d_in[8];
    const float* sv     = (const float*)d_in[9];
    float* out = (float*)d_out;

    float *a0, *a1, *b0;
    cudaGetSymbolAddress((void**)&a0, g_a0);
    cudaGetSymbolAddress((void**)&a1, g_a1);
    cudaGetSymbolAddress((void**)&b0, g_b0);

    cudaFuncSetAttribute(agg_kernel, cudaFuncAttributeMaxDynamicSharedMemorySize, SMEM_TOTAL);
    cudaFuncSetAttribute(final_kernel, cudaFuncAttributeMaxDynamicSharedMemorySize, FIN_SMEM);

    const int GRID = 148;   // 1 CTA/SM (210 KB smem), persistent tiles
    const int T_A = 320;    // 3200/10
    const int T_B = 3840;   // 38400/10
    const int T_C = 320;

    // Stages A+B merged (independent): tiles [0,320) -> a0, [320,4160) -> a1
    agg_kernel<<<GRID, NT, SMEM_TOTAL>>>(hidden, nh1, nw0, a0, T_A,
                                         nh1, nh2, nw1, a1, T_A + T_B, w1, w2);
    // Stage C: agg(a0, a1, nw0) -> b0   [320 tiles]
    agg_kernel<<<GRID, NT, SMEM_TOTAL>>>(a0, a1, nw0, b0, T_C,
                                         a0, a1, nw0, b0, T_C, w1, w2);
    // Final gating (persistent, weights in smem)
    final_kernel<<<GRID, 256, FIN_SMEM>>>(hidden, a0, b0, w3, w4, sv, out, 64*50);
}

// round 14
// speedup vs baseline: 1.1004x; 1.1004x over previous
#include <cuda_runtime.h>
#include <cuda_bf16.h>
#include <cstdint>

#define DIMD 128
#define SAMP 12
#define RPT  10            // item rows per tile (divides 3200 and 38400 exactly)
#define MROWS 120          // GEMM rows per tile (padded to 128 in the A planes)
#define NT   256           // 8 warps; warp grid 2(m)x4(n): m64 x n32 per warp

// ---- agg smem byte offsets (dynamic) ----
#define NB0_OFF   0          // nb fp32 [120][128], buffer 0              61440
#define NB1_OFF   61440      // buffer 1                                  61440
#define AHI_OFF   122880     // A bf16 hi [128][128] swizzled             32768
#define ALO_OFF   155648     // A bf16 lo                                 32768
#define IT0_OFF   188416     // item fp32 [10][128] buf0                   5120
#define IT1_OFF   193536     // buf1                                       5120
#define NW0_OFF   198656     // 120 floats buf0                             512
#define NW1_OFF   199168     // buf1                                        512
#define LGP_OFF   199680     // logit partials [8 warps][128]              4096
#define LG_OFF    207872     // 120 logits                                  512
#define AL_OFF    208384     // 120 alphas                                  512
#define BIAS_OFF  208896     // 128 floats (W1 row D)                       512
#define W2_OFF    209408     // 128 floats                                  512
#define SMEM_TOTAL 209920
// W1^T bf16 hi/lo staging overlaps the NB region (read once before the loop)
#define BSTG_HI   0
#define BSTG_LO   32768

static __device__ __forceinline__ uint32_t smem_u32(const void* p) {
    uint32_t a;
    asm("{ .reg .u64 t; cvta.to.shared.u64 t, %1; cvt.u32.u64 %0, t; }" : "=r"(a) : "l"(p));
    return a;
}
static __device__ __forceinline__ void ldsm4(uint32_t &r0, uint32_t &r1, uint32_t &r2, uint32_t &r3,
                                             uint32_t addr) {
    asm volatile("ldmatrix.sync.aligned.m8n8.x4.shared.b16 {%0,%1,%2,%3}, [%4];"
                 : "=r"(r0), "=r"(r1), "=r"(r2), "=r"(r3) : "r"(addr));
}
static __device__ __forceinline__ void mma_bf16(float* d, const uint32_t* a, uint32_t b0, uint32_t b1) {
    asm volatile("mma.sync.aligned.m16n8k16.row.col.f32.bf16.bf16.f32 "
                 "{%0,%1,%2,%3}, {%4,%5,%6,%7}, {%8,%9}, {%0,%1,%2,%3};"
                 : "+f"(d[0]), "+f"(d[1]), "+f"(d[2]), "+f"(d[3])
                 : "r"(a[0]), "r"(a[1]), "r"(a[2]), "r"(a[3]), "r"(b0), "r"(b1));
}
static __device__ __forceinline__ void cp16(uint32_t smem_addr, const void* gmem) {
    asm volatile("cp.async.cg.shared.global [%0], [%1], 16;" :: "r"(smem_addr), "l"(gmem));
}
static __device__ __forceinline__ void cp_commit() {
    asm volatile("cp.async.commit_group;" ::: "memory");
}
static __device__ __forceinline__ void cp_wait0() {
    asm volatile("cp.async.wait_group 0;" ::: "memory");
}

// ---- scratch (no allocations allowed: device globals) ----
__device__ float g_a0[64*50*128];
__device__ float g_a1[64*600*128];
__device__ float g_b0[64*50*128];

// Prefetch one tile's (nb, item, nw) into smem buffer via cp.async. NT=256.
static __device__ __forceinline__ void prefetch_tile(
    uint32_t smb, uint32_t nbo, uint32_t ito, uint32_t nwo,
    const float* __restrict__ item, const float* __restrict__ nb,
    const float* __restrict__ nw, int rowBase, int tid)
{
    const float4* nbsrc = (const float4*)nb + (size_t)rowBase*(SAMP*32);
    #pragma unroll
    for (int k = 0; k < 15; k++)                       // 3840 granules exactly
        cp16(smb + nbo + (uint32_t)(tid + k*NT)*16u, nbsrc + tid + k*NT);
    const float4* itsrc = (const float4*)item + (size_t)rowBase*32;
    cp16(smb + ito + (uint32_t)tid*16u, itsrc + tid);  // granules 0..255
    if (tid < 64) cp16(smb + ito + (uint32_t)(256 + tid)*16u, itsrc + 256 + tid);
    const float4* nwsrc = (const float4*)(nw + (size_t)rowBase*SAMP);
    if (tid < 30) cp16(smb + nwo + (uint32_t)tid*16u, nwsrc + tid);
}

// Two independent attention-aggregate stages in one persistent launch.
// Tiles [0, tiles0) use set 0; tiles [tiles0, tilesTotal) use set 1.
__global__ void __launch_bounds__(NT, 1)
agg_kernel(const float* __restrict__ item0, const float* __restrict__ nb0a,
           const float* __restrict__ nw0a,  float* __restrict__ out0, int tiles0,
           const float* __restrict__ item1, const float* __restrict__ nb1a,
           const float* __restrict__ nw1a,  float* __restrict__ out1, int tilesTotal,
           const float* __restrict__ w1,    const float* __restrict__ w2)
{
    extern __shared__ __align__(128) char sm[];
    const uint32_t smb = smem_u32(sm);
    const int tid  = threadIdx.x;
    const int lane = tid & 31;
    const int warp = tid >> 5;          // 0..7
    const int wm   = warp >> 2;         // m-half: rows [64wm, 64wm+64)
    const int wn   = warp & 3;          // n-slice: cols [32wn, 32wn+32)

    // ---- startup: stage W1^T hi/lo bf16 (swizzled) into the NB region ----
    for (int i = tid; i < DIMD*DIMD; i += NT) {
        int d = i >> 7, n = i & 127;                 // w1[d][n]
        float w = w1[i];
        __nv_bfloat16 hb = __float2bfloat16(w);
        __nv_bfloat16 lb = __float2bfloat16(w - __bfloat162float(hb));
        uint32_t off = (uint32_t)n*256u + ((uint32_t)(((d>>3) ^ (n & 7))) << 4) + ((uint32_t)(d & 7) << 1);
        *(__nv_bfloat16*)(sm + BSTG_HI + off) = hb;
        *(__nv_bfloat16*)(sm + BSTG_LO + off) = lb;
    }
    if (tid < DIMD) {
        ((float*)(sm + BIAS_OFF))[tid] = w1[DIMD*DIMD + tid];
        ((float*)(sm + W2_OFF))[tid]   = w2[tid];
    }
    __syncthreads();

    // ---- load B fragments for this warp's 4 n8-blocks into registers ----
    uint32_t bh[4][8][2], bl[4][8][2];
    {
        const uint32_t l7  = (uint32_t)(lane & 7);
        const uint32_t ck4 = ((uint32_t)lane >> 3) & 3;
        #pragma unroll
        for (int j = 0; j < 4; j++) {
            const uint32_t row8 = (uint32_t)(wn*32 + j*8) + l7;
            const uint32_t rOff = row8 * 256u;
            const uint32_t swz  = row8 & 7;
            #pragma unroll
            for (int p = 0; p < 4; p++) {
                const uint32_t term = rOff + ((((uint32_t)(4*p) + ck4) ^ swz) << 4);
                ldsm4(bh[j][2*p][0], bh[j][2*p][1], bh[j][2*p+1][0], bh[j][2*p+1][1], smb + BSTG_HI + term);
                ldsm4(bl[j][2*p][0], bl[j][2*p][1], bl[j][2*p+1][0], bl[j][2*p+1][1], smb + BSTG_LO + term);
            }
        }
    }
    __syncthreads();   // staging region free; becomes nb buffers

    // ---- zero A-plane rows 120..127 (never written per-tile) ----
    {
        const uint32_t plane = (tid < 128) ? AHI_OFF : ALO_OFF;
        const int idx = tid & 127;
        *(float4*)(sm + plane + 120*256 + idx*16) = make_float4(0.f,0.f,0.f,0.f);
    }

    const float* nwb[2]   = { (const float*)(sm + NW0_OFF), (const float*)(sm + NW1_OFF) };
    const float* nbb[2]   = { (const float*)(sm + NB0_OFF), (const float*)(sm + NB1_OFF) };
    const char*  itb[2]   = { sm + IT0_OFF, sm + IT1_OFF };
    const uint32_t nbOffB[2] = { NB0_OFF, NB1_OFF };
    const uint32_t itOffB[2] = { IT0_OFF, IT1_OFF };
    const uint32_t nwOffB[2] = { NW0_OFF, NW1_OFF };
    const float* biasf = (const float*)(sm + BIAS_OFF);
    const float* w2f   = (const float*)(sm + W2_OFF);
    float* lgpart = (float*)(sm + LGP_OFF);
    float* lgf    = (float*)(sm + LG_OFF);
    float* alf    = (float*)(sm + AL_OFF);

    const uint32_t aLaneRow = (uint32_t)(lane & 15) * 256u;
    const uint32_t aCk      = (uint32_t)(lane >> 4);
    const uint32_t aSwz     = (uint32_t)(lane & 7);

    // ---- preloop: prefetch first tile into buffer 0 ----
    {
        const int ti = blockIdx.x;
        const int rb = (ti < tiles0) ? ti*RPT : (ti - tiles0)*RPT;
        const float* it  = (ti < tiles0) ? item0 : item1;
        const float* nbp = (ti < tiles0) ? nb0a : nb1a;
        const float* nwp = (ti < tiles0) ? nw0a : nw1a;
        prefetch_tile(smb, NB0_OFF, IT0_OFF, NW0_OFF, it, nbp, nwp, rb, tid);
        cp_commit();
    }

    int cur = 0;
    for (int ti = blockIdx.x; ti < tilesTotal; ti += gridDim.x) {
        const int rowBase = (ti < tiles0) ? ti*RPT : (ti - tiles0)*RPT;
        float* outp = (ti < tiles0) ? out0 : out1;

        cp_wait0();
        __syncthreads();                 // buffer[cur] ready for all threads

        // ---- convert: A = bf16 hi/lo(item ⊙ nb) into swizzled planes ----
        {
            const float4* nbq = (const float4*)nbb[cur];
            const char* itc = itb[cur];
            #pragma unroll
            for (int k = 0; k < 15; k++) {           // 3840 granules exactly
                const int i = tid + k*NT;
                const int rs = i >> 5, j = i & 31;
                float4 v  = nbq[i];
                float4 it = *(const float4*)(itc + (size_t)(rs/SAMP)*512 + (size_t)j*16);
                float m0 = v.x*it.x, m1 = v.y*it.y, m2 = v.z*it.z, m3 = v.w*it.w;
                __nv_bfloat162 h01 = __floats2bfloat162_rn(m0, m1);
                __nv_bfloat162 h23 = __floats2bfloat162_rn(m2, m3);
                float2 f01 = __bfloat1622float2(h01);
                float2 f23 = __bfloat1622float2(h23);
                __nv_bfloat162 l01 = __floats2bfloat162_rn(m0 - f01.x, m1 - f01.y);
                __nv_bfloat162 l23 = __floats2bfloat162_rn(m2 - f23.x, m3 - f23.y);
                uint32_t off = (uint32_t)rs*256u + ((uint32_t)(((j>>1) ^ (rs & 7))) << 4) + ((uint32_t)(j & 1) << 3);
                *(__nv_bfloat162*)(sm + AHI_OFF + off)     = h01;
                *(__nv_bfloat162*)(sm + AHI_OFF + off + 4) = h23;
                *(__nv_bfloat162*)(sm + ALO_OFF + off)     = l01;
                *(__nv_bfloat162*)(sm + ALO_OFF + off + 4) = l23;
            }
        }
        __syncthreads();                 // A planes ready; buffer[cur^1] free

        // ---- prefetch next tile into buffer[cur^1] (overlaps MMA+epilogue) ----
        {
            const int tn = ti + gridDim.x;
            if (tn < tilesTotal) {
                const int rb2 = (tn < tiles0) ? tn*RPT : (tn - tiles0)*RPT;
                const float* it  = (tn < tiles0) ? item0 : item1;
                const float* nbp = (tn < tiles0) ? nb0a : nb1a;
                const float* nwp = (tn < tiles0) ? nw0a : nw1a;
                prefetch_tile(smb, nbOffB[cur^1], itOffB[cur^1], nwOffB[cur^1], it, nbp, nwp, rb2, tid);
                cp_commit();
            }
        }

        // ---- MMA: warp computes D[64wm:64wm+64, 32wn:32wn+32] ----
        // Term-major order over j breaks the 3-deep accumulator RAW chain.
        float d[4][4][4];
        #pragma unroll
        for (int s = 0; s < 4; s++)
            #pragma unroll
            for (int j = 0; j < 4; j++)
                #pragma unroll
                for (int i = 0; i < 4; i++) d[s][j][i] = 0.f;

        #pragma unroll
        for (int q = 0; q < 8; q++) {
            const uint32_t koff = ((((uint32_t)(2*q) + aCk) ^ aSwz) << 4);
            #pragma unroll
            for (int s = 0; s < 4; s++) {
                const uint32_t aoff = (uint32_t)(wm*4 + s)*4096u + aLaneRow + koff;
                uint32_t ah[4], al[4];
                ldsm4(ah[0], ah[1], ah[2], ah[3], smb + AHI_OFF + aoff);
                ldsm4(al[0], al[1], al[2], al[3], smb + ALO_OFF + aoff);
                #pragma unroll
                for (int j = 0; j < 4; j++) mma_bf16(d[s][j], ah, bh[j][q][0], bh[j][q][1]);
                #pragma unroll
                for (int j = 0; j < 4; j++) mma_bf16(d[s][j], al, bh[j][q][0], bh[j][q][1]);
                #pragma unroll
                for (int j = 0; j < 4; j++) mma_bf16(d[s][j], ah, bl[j][q][0], bl[j][q][1]);
            }
        }

        // ---- logit partials: bias*nw + leaky + dot(w2) over this warp's 32 cols ----
        {
            const int lq = lane & 3;
            const int rq = lane >> 2;
            const float* nwf = nwb[cur];
            #pragma unroll
            for (int s = 0; s < 4; s++) {
                const int r0 = wm*64 + s*16 + rq;
                const int r1 = r0 + 8;
                const float nw0 = nwf[r0];
                const float nw1 = nwf[r1 < MROWS ? r1 : 0];
                float lg0 = 0.f, lg1 = 0.f;
                #pragma unroll
                for (int j = 0; j < 4; j++) {
                    const int c0 = wn*32 + j*8 + lq*2;
                    const float b0v = biasf[c0], b1v = biasf[c0+1];
                    const float v0  = w2f[c0],   v1  = w2f[c0+1];
                    float y;
                    y = d[s][j][0] + nw0*b0v; y = fmaxf(y,0.f) + 0.2f*fminf(y,0.f); lg0 = fmaf(y, v0, lg0);
                    y = d[s][j][1] + nw0*b1v; y = fmaxf(y,0.f) + 0.2f*fminf(y,0.f); lg0 = fmaf(y, v1, lg0);
                    y = d[s][j][2] + nw1*b0v; y = fmaxf(y,0.f) + 0.2f*fminf(y,0.f); lg1 = fmaf(y, v0, lg1);
                    y = d[s][j][3] + nw1*b1v; y = fmaxf(y,0.f) + 0.2f*fminf(y,0.f); lg1 = fmaf(y, v1, lg1);
                }
                lg0 += __shfl_xor_sync(0xffffffffu, lg0, 1);
                lg0 += __shfl_xor_sync(0xffffffffu, lg0, 2);
                lg1 += __shfl_xor_sync(0xffffffffu, lg1, 1);
                lg1 += __shfl_xor_sync(0xffffffffu, lg1, 2);
                if (lq == 0) {
                    lgpart[warp*128 + r0] = lg0;
                    if (r1 < MROWS) lgpart[warp*128 + r1] = lg1;
                }
            }
        }
        __syncthreads();

        // ---- reduce partials across the 4 n-warps of each m-half, softmax ----
        if (tid < MROWS) {
            const int wmr = tid >> 6;
            float lg = 0.f;
            #pragma unroll
            for (int k = 0; k < 4; k++) lg += lgpart[(wmr*4 + k)*128 + tid];
            lgf[tid] = lg;
        }
        __syncthreads();
        if (tid < RPT) {
            const float* lg = lgf + tid*SAMP;
            float l[SAMP], mx = -1e30f;
            #pragma unroll
            for (int s = 0; s < SAMP; s++) { l[s] = lg[s]; mx = fmaxf(mx, l[s]); }
            float sum = 0.f;
            #pragma unroll
            for (int s = 0; s < SAMP; s++) { l[s] = __expf(l[s] - mx); sum += l[s]; }
            float inv = 1.f / sum;
            #pragma unroll
            for (int s = 0; s < SAMP; s++) alf[tid*SAMP + s] = l[s] * inv;
        }
        __syncthreads();

        // ---- weighted sum of raw nb rows from the prefetch buffer ----
        {
            const int col = tid & 127;
            const int grp = tid >> 7;           // 0..1
            const float* nbf = nbb[cur];
            #pragma unroll
            for (int r = grp; r < RPT; r += 2) {
                float acc = 0.f;
                #pragma unroll
                for (int s = 0; s < SAMP; s++)
                    acc = fmaf(alf[r*SAMP + s], nbf[(size_t)(r*SAMP + s)*DIMD + col], acc);
                outp[(size_t)(rowBase + r)*DIMD + col] = acc;
            }
        }
        __syncthreads();   // epilogue readers done before next convert overwrites
        cur ^= 1;
    }
}

// ============================================================================
// Final gating via MMA:  z = [h | agg] @ [w3; w4]  (K=256, bf16 3-term hi/lo)
//   agg = s0*a0 + s1*b0;  out = (1-sig(z))*h + sig(z)*agg
// 3200 rows = 25 tiles x 128 rows exactly. One CTA per tile, 8 warps.
// smem planes (each 128 rows x 256B): P0=k[0,128) (h), P1=k[128,256) (agg)
// ============================================================================
#define FP0_HI 0
#define FP1_HI 32768
#define FP0_LO 65536
#define FP1_LO 98304
#define FSMEM  131072

__global__ void __launch_bounds__(256, 1)
final_mma(const float* __restrict__ hidden,
          const float* __restrict__ a0,
          const float* __restrict__ b0,
          const float* __restrict__ w3,
          const float* __restrict__ w4,
          const float* __restrict__ sw,
          float* __restrict__ out)
{
    extern __shared__ __align__(128) char sm[];
    const uint32_t smb = smem_u32(sm);
    const int tid  = threadIdx.x;
    const int lane = tid & 31;
    const int warp = tid >> 5;
    const int wm   = warp >> 2;         // m-half
    const int wn   = warp & 3;          // n-slice (32 cols)
    const int tileBase = blockIdx.x * 128;

    const float s0 = __ldg(&sw[0]);
    const float s1 = __ldg(&sw[1]);

    // ---- stage B = [w3; w4]^T hi/lo into the plane region ----
    for (int i = tid; i < DIMD*DIMD; i += 256) {
        int d = i >> 7, n = i & 127;
        uint32_t off = (uint32_t)n*256u + ((uint32_t)(((d>>3) ^ (n & 7))) << 4) + ((uint32_t)(d & 7) << 1);
        float w = w3[i];                                      // w3[d][n] -> k=d
        __nv_bfloat16 hb = __float2bfloat16(w);
        __nv_bfloat16 lb = __float2bfloat16(w - __bfloat162float(hb));
        *(__nv_bfloat16*)(sm + FP0_HI + off) = hb;
        *(__nv_bfloat16*)(sm + FP0_LO + off) = lb;
        w = w4[i];                                            // w4[d][n] -> k=128+d
        hb = __float2bfloat16(w);
        lb = __float2bfloat16(w - __bfloat162float(hb));
        *(__nv_bfloat16*)(sm + FP1_HI + off) = hb;
        *(__nv_bfloat16*)(sm + FP1_LO + off) = lb;
    }
    __syncthreads();

    // ---- load B fragments: 4 n8-blocks x 16 q (q<8 from P0=w3, q>=8 from P1=w4) ----
    uint32_t bh[4][16][2], bl[4][16][2];
    {
        const uint32_t l7  = (uint32_t)(lane & 7);
        const uint32_t ck4 = ((uint32_t)lane >> 3) & 3;
        #pragma unroll
        for (int j = 0; j < 4; j++) {
            const uint32_t row8 = (uint32_t)(wn*32 + j*8) + l7;
            const uint32_t rOff = row8 * 256u;
            const uint32_t swz  = row8 & 7;
            #pragma unroll
            for (int p = 0; p < 4; p++) {
                const uint32_t term = rOff + ((((uint32_t)(4*p) + ck4) ^ swz) << 4);
                ldsm4(bh[j][2*p][0], bh[j][2*p][1], bh[j][2*p+1][0], bh[j][2*p+1][1], smb + FP0_HI + term);
                ldsm4(bl[j][2*p][0], bl[j][2*p][1], bl[j][2*p+1][0], bl[j][2*p+1][1], smb + FP0_LO + term);
                ldsm4(bh[j][8+2*p][0], bh[j][8+2*p][1], bh[j][9+2*p][0], bh[j][9+2*p][1], smb + FP1_HI + term);
                ldsm4(bl[j][8+2*p][0], bl[j][8+2*p][1], bl[j][9+2*p][0], bl[j][9+2*p][1], smb + FP1_LO + term);
            }
        }
    }
    __syncthreads();   // staging consumed; planes become A

    // ---- convert A: row r, plane0 = h (k<128), plane1 = agg (k>=128) ----
    {
        const int r = tid >> 1;
        const int half = tid & 1;
        const uint32_t hiOff = half ? FP1_HI : FP0_HI;
        const uint32_t loOff = half ? FP1_LO : FP0_LO;
        const float4* src  = (const float4*)(hidden + (size_t)(tileBase + r)*DIMD);
        const float4* srcA = (const float4*)(a0 + (size_t)(tileBase + r)*DIMD);
        const float4* srcB = (const float4*)(b0 + (size_t)(tileBase + r)*DIMD);
        #pragma unroll 4
        for (int g = 0; g < 32; g++) {
            float4 v;
            if (half == 0) {
                v = src[g];
            } else {
                float4 va = srcA[g], vb = srcB[g];
                v.x = fmaf(va.x, s0, vb.x*s1); v.y = fmaf(va.y, s0, vb.y*s1);
                v.z = fmaf(va.z, s0, vb.z*s1); v.w = fmaf(va.w, s0, vb.w*s1);
            }
            __nv_bfloat162 h01 = __floats2bfloat162_rn(v.x, v.y);
            __nv_bfloat162 h23 = __floats2bfloat162_rn(v.z, v.w);
            float2 f01 = __bfloat1622float2(h01);
            float2 f23 = __bfloat1622float2(h23);
            __nv_bfloat162 l01 = __floats2bfloat162_rn(v.x - f01.x, v.y - f01.y);
            __nv_bfloat162 l23 = __floats2bfloat162_rn(v.z - f23.x, v.w - f23.y);
            uint32_t off = (uint32_t)r*256u + ((uint32_t)(((g>>1) ^ (r & 7))) << 4) + ((uint32_t)(g & 1) << 3);
            *(__nv_bfloat162*)(sm + hiOff + off)     = h01;
            *(__nv_bfloat162*)(sm + hiOff + off + 4) = h23;
            *(__nv_bfloat162*)(sm + loOff + off)     = l01;
            *(__nv_bfloat162*)(sm + loOff + off + 4) = l23;
        }
    }
    __syncthreads();

    // ---- MMA over K=256 ----
    const uint32_t aLaneRow = (uint32_t)(lane & 15) * 256u;
    const uint32_t aCk      = (uint32_t)(lane >> 4);
    const uint32_t aSwz     = (uint32_t)(lane & 7);

    float d[4][4][4];
    #pragma unroll
    for (int s = 0; s < 4; s++)
        #pragma unroll
        for (int j = 0; j < 4; j++)
            #pragma unroll
            for (int i = 0; i < 4; i++) d[s][j][i] = 0.f;

    #pragma unroll
    for (int q = 0; q < 16; q++) {
        const uint32_t hiBase = (q < 8) ? FP0_HI : FP1_HI;
        const uint32_t loBase = (q < 8) ? FP0_LO : FP1_LO;
        const uint32_t koff = ((((uint32_t)(2*(q & 7)) + aCk) ^ aSwz) << 4);
        #pragma unroll
        for (int s = 0; s < 4; s++) {
            const uint32_t aoff = (uint32_t)(wm*4 + s)*4096u + aLaneRow + koff;
            uint32_t ah[4], al[4];
            ldsm4(ah[0], ah[1], ah[2], ah[3], smb + hiBase + aoff);
            ldsm4(al[0], al[1], al[2], al[3], smb + loBase + aoff);
            #pragma unroll
            for (int j = 0; j < 4; j++) mma_bf16(d[s][j], ah, bh[j][q][0], bh[j][q][1]);
            #pragma unroll
            for (int j = 0; j < 4; j++) mma_bf16(d[s][j], al, bh[j][q][0], bh[j][q][1]);
            #pragma unroll
            for (int j = 0; j < 4; j++) mma_bf16(d[s][j], ah, bl[j][q][0], bl[j][q][1]);
        }
    }

    // ---- epilogue: sig = sigmoid(z); out = (1-sig)*h + sig*agg ----
    {
        const int lq = lane & 3;
        const int rq = lane >> 2;
        #pragma unroll
        for (int s = 0; s < 4; s++) {
            #pragma unroll
            for (int j = 0; j < 4; j++) {
                const int c0 = wn*32 + j*8 + lq*2;
                const int g  = c0 >> 2;
                const uint32_t pairAdd = ((uint32_t)((c0 >> 1) & 1)) << 2;
                #pragma unroll
                for (int half = 0; half < 2; half++) {
                    const int row = wm*64 + s*16 + rq + half*8;
                    const uint32_t off = (uint32_t)row*256u
                        + ((uint32_t)(((g>>1) ^ (row & 7))) << 4)
                        + ((uint32_t)(g & 1) << 3) + pairAdd;
                    float2 hhi = __bfloat1622float2(*(__nv_bfloat162*)(sm + FP0_HI + off));
                    float2 hlo = __bfloat1622float2(*(__nv_bfloat162*)(sm + FP0_LO + off));
                    float2 ghi = __bfloat1622float2(*(__nv_bfloat162*)(sm + FP1_HI + off));
                    float2 glo = __bfloat1622float2(*(__nv_bfloat162*)(sm + FP1_LO + off));
                    const float h0 = hhi.x + hlo.x, h1 = hhi.y + hlo.y;
                    const float a0v = ghi.x + glo.x, a1v = ghi.y + glo.y;
                    const float z0 = d[s][j][half*2 + 0];
                    const float z1 = d[s][j][half*2 + 1];
                    const float sg0 = 1.f / (1.f + __expf(-z0));
                    const float sg1 = 1.f / (1.f + __expf(-z1));
                    float2 o;
                    o.x = (1.f - sg0)*h0 + sg0*a0v;
                    o.y = (1.f - sg1)*h1 + sg1*a1v;
                    *(float2*)(out + (size_t)(tileBase + row)*DIMD + c0) = o;
                }
            }
        }
    }
}

extern "C" void kernel_launch(void* const* d_in, const int* in_sizes, int n_in,
                              void* d_out, int out_size)
{
    const float* hidden = (const float*)d_in[0];
    const float* nh1    = (const float*)d_in[1];
    const float* nh2    = (const float*)d_in[2];
    const float* nw0    = (const float*)d_in[3];
    const float* nw1    = (const float*)d_in[4];
    const float* w1     = (const float*)d_in[5];
    const float* w2     = (const float*)d_in[6];
    const float* w3     = (const float*)d_in[7];
    const float* w4     = (const float*)d_in[8];
    const float* sv     = (const float*)d_in[9];
    float* out = (float*)d_out;

    float *a0, *a1, *b0;
    cudaGetSymbolAddress((void**)&a0, g_a0);
    cudaGetSymbolAddress((void**)&a1, g_a1);
    cudaGetSymbolAddress((void**)&b0, g_b0);

    cudaFuncSetAttribute(agg_kernel, cudaFuncAttributeMaxDynamicSharedMemorySize, SMEM_TOTAL);
    cudaFuncSetAttribute(final_mma, cudaFuncAttributeMaxDynamicSharedMemorySize, FSMEM);

    const int GRID = 148;   // 1 CTA/SM (210 KB smem), persistent tiles
    const int T_A = 320;    // 3200/10
    const int T_B = 3840;   // 38400/10
    const int T_C = 320;

    // Stages A+B merged (independent): tiles [0,320) -> a0, [320,4160) -> a1
    agg_kernel<<<GRID, NT, SMEM_TOTAL>>>(hidden, nh1, nw0, a0, T_A,
                                         nh1, nh2, nw1, a1, T_A + T_B, w1, w2);
    // Stage C: agg(a0, a1, nw0) -> b0   [320 tiles]
    agg_kernel<<<GRID, NT, SMEM_TOTAL>>>(a0, a1, nw0, b0, T_C,
                                         a0, a1, nw0, b0, T_C, w1, w2);
    // Final gating via MMA: 25 tiles of 128 rows
    final_mma<<<25, 256, FSMEM>>>(hidden, a0, b0, w3, w4, sv, out);
}